// round 2
// baseline (speedup 1.0000x reference)
#include <cuda_runtime.h>

#define SLEN 1024
#define BATCH 256
#define DIN 64
#define HID 128

// h outputs: [dir][b][t][j]  (256 MB scratch)
__device__ float g_h[2u * BATCH * SLEN * HID];

typedef unsigned long long u64;

__device__ __forceinline__ u64 pack2(float lo, float hi) {
    u64 r; asm("mov.b64 %0, {%1, %2};" : "=l"(r) : "f"(lo), "f"(hi)); return r;
}
__device__ __forceinline__ void fma2(u64 &d, u64 a, u64 b) {
    asm("fma.rn.f32x2 %0, %1, %2, %0;" : "+l"(d) : "l"(a), "l"(b));
}
__device__ __forceinline__ float sum2(u64 v) {
    float lo, hi; asm("mov.b64 {%0, %1}, %2;" : "=f"(lo), "=f"(hi) : "l"(v));
    return lo + hi;
}
// tanh(x) = 1 - 2/(exp2(2*log2(e)*x) + 1)
__device__ __forceinline__ float fast_tanh(float x) {
    float e, r;
    asm("ex2.approx.f32 %0, %1;" : "=f"(e) : "f"(x * 2.8853900817779268f));
    asm("rcp.approx.f32 %0, %1;" : "=f"(r) : "f"(e + 1.0f));
    return fmaf(-2.0f, r, 1.0f);
}

// 384 threads: tid = ks*128 + j.  ks in {0,1,2} selects 64-float K-chunk of the
// combined state [h(128) | x(64)].  Each thread holds 64 weight floats (32 u64)
// in registers and computes partial dot products for 4 batch rows.
__global__ __launch_bounds__(384, 1)
void birnn_recur(const float* __restrict__ inputs,
                 const float* __restrict__ Wih_fw, const float* __restrict__ Whh_fw,
                 const float* __restrict__ bih_fw, const float* __restrict__ bhh_fw,
                 const float* __restrict__ Wih_bw, const float* __restrict__ Whh_bw,
                 const float* __restrict__ bih_bw, const float* __restrict__ bhh_bw)
{
    __shared__ __align__(16) float kbuf[2][4][192];   // [buf][batch][h|x]
    __shared__ float psum[3][4][128];                 // [ks][batch][j]

    const int tid = threadIdx.x;
    const int j   = tid & 127;
    const int ks  = tid >> 7;                 // 0..2
    const int dir = blockIdx.x >> 6;
    const int bb  = (blockIdx.x & 63) * 4;    // batch base

    const float* Wih = dir ? Wih_bw : Wih_fw;
    const float* Whh = dir ? Whh_bw : Whh_fw;

    // ---- weights: 64 consecutive floats -> 32 f32x2 registers ----
    u64 w2[32];
    const float4* wrow = (ks < 2) ? (const float4*)(Whh + j * HID + ks * 64)
                                  : (const float4*)(Wih + j * DIN);
    #pragma unroll
    for (int q = 0; q < 16; ++q) {
        float4 v = __ldg(wrow + q);
        w2[2*q]   = pack2(v.x, v.y);
        w2[2*q+1] = pack2(v.z, v.w);
    }

    float bias_j = 0.0f;
    if (tid < HID)
        bias_j = dir ? (bih_bw[j] + bhh_bw[j]) : (bih_fw[j] + bhh_fw[j]);

    // ---- init state buffer 0: h = 0, x = x(t0) ----
    for (int i = tid; i < 2 * 4 * 192; i += 384) (&kbuf[0][0][0])[i] = 0.0f;

    const int dt = dir ? -1 : 1;
    const int t0 = dir ? (SLEN - 1) : 0;

    int xb = 0, xd = 0;
    const float* xptr = nullptr;
    if (tid >= 128) {                          // 256 x-loader threads
        xb = (tid - 128) >> 6;                 // batch 0..3
        xd = (tid - 128) & 63;                 // d 0..63
        xptr = inputs + (size_t)(bb + xb) * (SLEN * DIN) + t0 * DIN + xd;
    }
    __syncthreads();
    if (tid >= 128) kbuf[0][xb][HID + xd] = __ldg(xptr);
    __syncthreads();

    float* ghp = nullptr;
    if (tid < HID)
        ghp = g_h + ((size_t)(dir * BATCH + bb) * SLEN + t0) * HID + j;
    const int gh_bstride = SLEN * HID;
    const int gh_tstride = dt * HID;

    int p = 0;
    for (int step = 0; step < SLEN; ++step) {
        // prefetch next x early; ~768 cycles of FMA below hide the latency
        float xn = 0.0f;
        if (tid >= 128 && step + 1 < SLEN) {
            xptr += dt * DIN;
            xn = __ldg(xptr);
        }

        // partial dot products over this thread's 64-float K chunk, 4 batches
        u64 aP0=0, aP1=0, aP2=0, aP3=0, aQ0=0, aQ1=0, aQ2=0, aQ3=0;
        const float* kb = &kbuf[p][0][ks * 64];
        #pragma unroll
        for (int q = 0; q < 16; ++q) {
            ulonglong2 s0 = *(const ulonglong2*)(kb + 0 * 192 + q * 4);
            ulonglong2 s1 = *(const ulonglong2*)(kb + 1 * 192 + q * 4);
            ulonglong2 s2 = *(const ulonglong2*)(kb + 2 * 192 + q * 4);
            ulonglong2 s3 = *(const ulonglong2*)(kb + 3 * 192 + q * 4);
            fma2(aP0, s0.x, w2[2*q]);  fma2(aQ0, s0.y, w2[2*q+1]);
            fma2(aP1, s1.x, w2[2*q]);  fma2(aQ1, s1.y, w2[2*q+1]);
            fma2(aP2, s2.x, w2[2*q]);  fma2(aQ2, s2.y, w2[2*q+1]);
            fma2(aP3, s3.x, w2[2*q]);  fma2(aQ3, s3.y, w2[2*q+1]);
        }
        psum[ks][0][j] = sum2(aP0) + sum2(aQ0);
        psum[ks][1][j] = sum2(aP1) + sum2(aQ1);
        psum[ks][2][j] = sum2(aP2) + sum2(aQ2);
        psum[ks][3][j] = sum2(aP3) + sum2(aQ3);
        __syncthreads();

        if (tid < HID) {
            // combine K-split partials, activate, write h_{t+1} + stream to gmem
            #pragma unroll
            for (int b = 0; b < 4; ++b) {
                float a = bias_j + psum[0][b][j] + psum[1][b][j] + psum[2][b][j];
                float v = fast_tanh(a);
                kbuf[p ^ 1][b][j] = v;
                ghp[b * gh_bstride] = v;
            }
            ghp += gh_tstride;
        } else {
            kbuf[p ^ 1][xb][HID + xd] = xn;   // x for next step
        }
        __syncthreads();
        p ^= 1;
    }
}

// fc head: out[b][t] = fcb + sum_j h_fw[b][t][j]*fcW[j] + h_bw[b][t][j]*fcW[128+j]
// One warp per (b,t); lane reads a float4 per direction.
__global__ __launch_bounds__(256)
void birnn_fc(const float* __restrict__ fcW, const float* __restrict__ fcb,
              float* __restrict__ out)
{
    const int gw   = (blockIdx.x * blockDim.x + threadIdx.x) >> 5;  // (b,t) index
    const int lane = threadIdx.x & 31;
    const int b = gw >> 10;
    const int t = gw & 1023;

    const float4* hf = (const float4*)(g_h + ((size_t)b * SLEN + t) * HID);
    const float4* hb = (const float4*)(g_h + ((size_t)(BATCH + b) * SLEN + t) * HID);
    float4 a  = hf[lane];
    float4 c  = hb[lane];
    float4 wa = ((const float4*)fcW)[lane];
    float4 wb = ((const float4*)fcW)[32 + lane];

    float s = a.x*wa.x + a.y*wa.y + a.z*wa.z + a.w*wa.w
            + c.x*wb.x + c.y*wb.y + c.z*wb.z + c.w*wb.w;
    #pragma unroll
    for (int m = 16; m > 0; m >>= 1)
        s += __shfl_xor_sync(0xffffffffu, s, m);
    if (lane == 0) out[gw] = s + fcb[0];
}

extern "C" void kernel_launch(void* const* d_in, const int* in_sizes, int n_in,
                              void* d_out, int out_size)
{
    (void)in_sizes; (void)n_in; (void)out_size;
    const float* inputs = (const float*)d_in[0];
    const float* Wih_fw = (const float*)d_in[1];
    const float* Whh_fw = (const float*)d_in[2];
    const float* bih_fw = (const float*)d_in[3];
    const float* bhh_fw = (const float*)d_in[4];
    const float* Wih_bw = (const float*)d_in[5];
    const float* Whh_bw = (const float*)d_in[6];
    const float* bih_bw = (const float*)d_in[7];
    const float* bhh_bw = (const float*)d_in[8];
    const float* fcW    = (const float*)d_in[9];
    const float* fcb    = (const float*)d_in[10];
    float* out = (float*)d_out;

    birnn_recur<<<128, 384>>>(inputs,
                              Wih_fw, Whh_fw, bih_fw, bhh_fw,
                              Wih_bw, Whh_bw, bih_bw, bhh_bw);

    // BATCH*SLEN warps, 8 warps per block
    birnn_fc<<<(BATCH * SLEN) / 8, 256>>>(fcW, fcb, out);
}

// round 3
// speedup vs baseline: 1.1511x; 1.1511x over previous
#include <cuda_runtime.h>
#include <cuda_bf16.h>
#include <cstdint>

#define SLEN 1024
#define BATCH 256
#define DIN 64
#define HID 128

// 256 MB scratch: holds xp[dir][b][t][j] (phase 1), overwritten in-place with
// h[dir][b][t][j] by the recurrence (phase 2), consumed by the fc pass (phase 3).
__device__ float g_buf[2u * BATCH * SLEN * HID];

typedef unsigned long long u64;

static __device__ __forceinline__ u64 pack2(float lo, float hi) {
    u64 r; asm("mov.b64 %0, {%1, %2};" : "=l"(r) : "f"(lo), "f"(hi)); return r;
}
static __device__ __forceinline__ void fma2(u64 &d, u64 a, u64 b) {
    asm("fma.rn.f32x2 %0, %1, %2, %0;" : "+l"(d) : "l"(a), "l"(b));
}
static __device__ __forceinline__ float sum2(u64 v) {
    float lo, hi; asm("mov.b64 {%0, %1}, %2;" : "=f"(lo), "=f"(hi) : "l"(v));
    return lo + hi;
}
static __device__ __forceinline__ float fast_tanh(float x) {
    float e, r;
    asm("ex2.approx.f32 %0, %1;" : "=f"(e) : "f"(x * 2.8853900817779268f));
    asm("rcp.approx.f32 %0, %1;" : "=f"(r) : "f"(e + 1.0f));
    return fmaf(-2.0f, r, 1.0f);
}

// pack two f32 -> bf16x2 register (lo16 = a0, hi16 = a1)
static __device__ __forceinline__ uint32_t bfpack(float a0, float a1) {
    uint32_t r; asm("cvt.rn.bf16x2.f32 %0, %1, %2;" : "=r"(r) : "f"(a1), "f"(a0)); return r;
}
static __device__ __forceinline__ float bfres(float a) {
    return a - __bfloat162float(__float2bfloat16(a));
}
static __device__ __forceinline__ void mma16816(float c[4], const uint32_t a[4], const uint32_t b[2]) {
    asm("mma.sync.aligned.m16n8k16.row.col.f32.bf16.bf16.f32 "
        "{%0,%1,%2,%3}, {%4,%5,%6,%7}, {%8,%9}, {%0,%1,%2,%3};"
        : "+f"(c[0]), "+f"(c[1]), "+f"(c[2]), "+f"(c[3])
        : "r"(a[0]), "r"(a[1]), "r"(a[2]), "r"(a[3]), "r"(b[0]), "r"(b[1]));
}

// ===== Phase 1: xp[dir][b][t][j] = sum_d x[b][t][d] * Wih[dir][j][d]
// Tensor-core GEMM, fp32 emulated as bf16 hi/lo (hh + hl + lh products).
// Block tile: 128 rows((b,t)) x 128 cols(j), one dir per blockIdx.y.
// 8 warps in 4(M) x 2(N); warp tile 32x64; K=64 in 4 chunks of 16.
__global__ __launch_bounds__(256)
void xp_gemm(const float* __restrict__ x,
             const float* __restrict__ Wih_fw, const float* __restrict__ Wih_bw)
{
    const int lane = threadIdx.x & 31;
    const int wid  = threadIdx.x >> 5;
    const int wm = wid & 3, wn = wid >> 2;
    const int dir = blockIdx.y;
    const float* W = dir ? Wih_bw : Wih_fw;
    const size_t Mbase = (size_t)blockIdx.x * 128;

    const int rA = lane >> 2;          // fragment row / B col within 8-group
    const int kA = (lane & 3) * 2;     // fragment k pair

    float acc[2][8][4];
    #pragma unroll
    for (int mt = 0; mt < 2; ++mt)
        #pragma unroll
        for (int nt = 0; nt < 8; ++nt)
            #pragma unroll
            for (int c = 0; c < 4; ++c) acc[mt][nt][c] = 0.0f;

    #pragma unroll
    for (int kc = 0; kc < 4; ++kc) {
        const int kb = kc * 16;

        // B fragments (W[j][k], col-major k x n view): hi + lo
        uint32_t bh[8][2], bl[8][2];
        #pragma unroll
        for (int nt = 0; nt < 8; ++nt) {
            const int n = wn * 64 + nt * 8 + rA;
            const float* wp = W + n * DIN + kb + kA;
            float2 v0 = *(const float2*)wp;         // k, k+1
            float2 v1 = *(const float2*)(wp + 8);   // k+8, k+9
            bh[nt][0] = bfpack(v0.x, v0.y);
            bh[nt][1] = bfpack(v1.x, v1.y);
            bl[nt][0] = bfpack(bfres(v0.x), bfres(v0.y));
            bl[nt][1] = bfpack(bfres(v1.x), bfres(v1.y));
        }

        // A fragments (x rows): hi + lo
        uint32_t ah[2][4], al[2][4];
        #pragma unroll
        for (int mt = 0; mt < 2; ++mt) {
            const size_t r = Mbase + wm * 32 + mt * 16 + rA;
            const float* xp = x + r * DIN + kb + kA;
            float2 u0 = *(const float2*)(xp);
            float2 u1 = *(const float2*)(xp + 8 * DIN);
            float2 u2 = *(const float2*)(xp + 8);
            float2 u3 = *(const float2*)(xp + 8 * DIN + 8);
            ah[mt][0] = bfpack(u0.x, u0.y);  al[mt][0] = bfpack(bfres(u0.x), bfres(u0.y));
            ah[mt][1] = bfpack(u1.x, u1.y);  al[mt][1] = bfpack(bfres(u1.x), bfres(u1.y));
            ah[mt][2] = bfpack(u2.x, u2.y);  al[mt][2] = bfpack(bfres(u2.x), bfres(u2.y));
            ah[mt][3] = bfpack(u3.x, u3.y);  al[mt][3] = bfpack(bfres(u3.x), bfres(u3.y));
        }

        #pragma unroll
        for (int mt = 0; mt < 2; ++mt)
            #pragma unroll
            for (int nt = 0; nt < 8; ++nt) {
                mma16816(acc[mt][nt], ah[mt], bh[nt]);   // hi*hi
                mma16816(acc[mt][nt], ah[mt], bl[nt]);   // hi*lo
                mma16816(acc[mt][nt], al[mt], bh[nt]);   // lo*hi
            }
    }

    // epilogue: scatter to g_buf[dir][b][t][j]
    #pragma unroll
    for (int mt = 0; mt < 2; ++mt) {
        const size_t r0 = Mbase + wm * 32 + mt * 16 + (lane >> 2);
        const size_t r1 = r0 + 8;
        const int b0_ = (int)(r0 >> 10), t0_ = (int)(r0 & 1023);
        const int b1_ = (int)(r1 >> 10), t1_ = (int)(r1 & 1023);
        #pragma unroll
        for (int nt = 0; nt < 8; ++nt) {
            const int col = wn * 64 + nt * 8 + (lane & 3) * 2;
            float2* o0 = (float2*)(g_buf + ((size_t)(dir * BATCH + b0_) * SLEN + t0_) * HID + col);
            float2* o1 = (float2*)(g_buf + ((size_t)(dir * BATCH + b1_) * SLEN + t1_) * HID + col);
            *o0 = make_float2(acc[mt][nt][0], acc[mt][nt][1]);
            *o1 = make_float2(acc[mt][nt][2], acc[mt][nt][3]);
        }
    }
}

// ===== Phase 2: recurrence, K=128 only. 128 blocks x 256 threads.
// Thread owns output unit j for 2 batch rows; Whh row j in 64 f32x2 registers.
__global__ __launch_bounds__(256, 1)
void birnn_recur(const float* __restrict__ Whh_fw, const float* __restrict__ Whh_bw,
                 const float* __restrict__ bih_fw, const float* __restrict__ bhh_fw,
                 const float* __restrict__ bih_bw, const float* __restrict__ bhh_bw)
{
    __shared__ __align__(16) float kbuf[2][4][HID];

    const int tid  = threadIdx.x;
    const int j    = tid & 127;
    const int half = tid >> 7;
    const int dir  = blockIdx.x >> 6;
    const int bb   = (blockIdx.x & 63) * 4;
    const int b0   = half * 2, b1 = half * 2 + 1;

    const float* Whh = dir ? Whh_bw : Whh_fw;
    u64 w2[64];
    const float4* wr = (const float4*)(Whh + j * HID);
    #pragma unroll
    for (int q = 0; q < 32; ++q) {
        float4 v = __ldg(wr + q);
        w2[2*q]   = pack2(v.x, v.y);
        w2[2*q+1] = pack2(v.z, v.w);
    }
    const float bias = dir ? (bih_bw[j] + bhh_bw[j]) : (bih_fw[j] + bhh_fw[j]);

    for (int i = tid; i < 4 * HID; i += 256) (&kbuf[0][0][0])[i] = 0.0f;

    const int dt = dir ? -1 : 1;
    const int t0 = dir ? (SLEN - 1) : 0;
    const long stride = (long)dt * HID;

    float* p0 = g_buf + ((size_t)(dir * BATCH + bb + b0) * SLEN + t0) * HID + j;
    float* p1 = g_buf + ((size_t)(dir * BATCH + bb + b1) * SLEN + t0) * HID + j;
    float xc0 = __ldg(p0);
    float xc1 = __ldg(p1);
    __syncthreads();

    int p = 0;
    for (int step = 0; step < SLEN; ++step) {
        // prefetch next step's xp (hidden under the FMA block below)
        float xn0 = 0.0f, xn1 = 0.0f;
        if (step + 1 < SLEN) { xn0 = __ldg(p0 + stride); xn1 = __ldg(p1 + stride); }

        u64 aP0 = 0, aQ0 = 0, aP1 = 0, aQ1 = 0;
        const float* kb0 = &kbuf[p][b0][0];
        const float* kb1 = &kbuf[p][b1][0];
        #pragma unroll
        for (int q = 0; q < 32; ++q) {
            ulonglong2 s0 = *(const ulonglong2*)(kb0 + q * 4);
            ulonglong2 s1 = *(const ulonglong2*)(kb1 + q * 4);
            fma2(aP0, s0.x, w2[2*q]);  fma2(aQ0, s0.y, w2[2*q+1]);
            fma2(aP1, s1.x, w2[2*q]);  fma2(aQ1, s1.y, w2[2*q+1]);
        }
        float v0 = fast_tanh(xc0 + bias + sum2(aP0) + sum2(aQ0));
        float v1 = fast_tanh(xc1 + bias + sum2(aP1) + sum2(aQ1));

        __syncthreads();   // everyone done reading kbuf[p]

        kbuf[p ^ 1][b0][j] = v0;
        kbuf[p ^ 1][b1][j] = v1;
        *p0 = v0;          // overwrite xp[t] (already consumed) with h[t]
        *p1 = v1;
        p0 += stride; p1 += stride;
        xc0 = xn0; xc1 = xn1;

        __syncthreads();
        p ^= 1;
    }
}

// ===== Phase 3: fc head. out[b][t] = fcb + <h_fw, fcW[0:128]> + <h_bw, fcW[128:256]>
__global__ __launch_bounds__(256)
void birnn_fc(const float* __restrict__ fcW, const float* __restrict__ fcb,
              float* __restrict__ out)
{
    const int gw   = (blockIdx.x * blockDim.x + threadIdx.x) >> 5;
    const int lane = threadIdx.x & 31;
    const int b = gw >> 10;
    const int t = gw & 1023;

    const float4* hf = (const float4*)(g_buf + ((size_t)b * SLEN + t) * HID);
    const float4* hb = (const float4*)(g_buf + ((size_t)(BATCH + b) * SLEN + t) * HID);
    float4 a  = hf[lane];
    float4 c  = hb[lane];
    float4 wa = ((const float4*)fcW)[lane];
    float4 wb = ((const float4*)fcW)[32 + lane];

    float s = a.x*wa.x + a.y*wa.y + a.z*wa.z + a.w*wa.w
            + c.x*wb.x + c.y*wb.y + c.z*wb.z + c.w*wb.w;
    #pragma unroll
    for (int m = 16; m > 0; m >>= 1)
        s += __shfl_xor_sync(0xffffffffu, s, m);
    if (lane == 0) out[gw] = s + fcb[0];
}

extern "C" void kernel_launch(void* const* d_in, const int* in_sizes, int n_in,
                              void* d_out, int out_size)
{
    (void)in_sizes; (void)n_in; (void)out_size;
    const float* inputs = (const float*)d_in[0];
    const float* Wih_fw = (const float*)d_in[1];
    const float* Whh_fw = (const float*)d_in[2];
    const float* bih_fw = (const float*)d_in[3];
    const float* bhh_fw = (const float*)d_in[4];
    const float* Wih_bw = (const float*)d_in[5];
    const float* Whh_bw = (const float*)d_in[6];
    const float* bih_bw = (const float*)d_in[7];
    const float* bhh_bw = (const float*)d_in[8];
    const float* fcW    = (const float*)d_in[9];
    const float* fcb    = (const float*)d_in[10];
    float* out = (float*)d_out;

    // phase 1: input projection on tensor cores (bf16 hi/lo emulated fp32)
    xp_gemm<<<dim3(BATCH * SLEN / 128, 2), 256>>>(inputs, Wih_fw, Wih_bw);

    // phase 2: recurrence (K=128 scalar FMA floor)
    birnn_recur<<<128, 256>>>(Whh_fw, Whh_bw, bih_fw, bhh_fw, bih_bw, bhh_bw);

    // phase 3: fc head (HBM-bound streaming pass)
    birnn_fc<<<(BATCH * SLEN) / 8, 256>>>(fcW, fcb, out);
}

// round 4
// speedup vs baseline: 1.1538x; 1.0023x over previous
#include <cuda_runtime.h>
#include <cuda_bf16.h>
#include <cstdint>

#define SLEN 1024
#define BATCH 256
#define DIN 64
#define HID 128

// xp (phase 1) then h (phase 2), layout [dir][bg(32)][t(1024)][bi(8)][j(128)]
__device__ float g_buf[2u * BATCH * SLEN * HID];

// pack two f32 -> bf16x2 (lo16 = a0, hi16 = a1)
static __device__ __forceinline__ uint32_t bfpack(float a0, float a1) {
    uint32_t r; asm("cvt.rn.bf16x2.f32 %0, %1, %2;" : "=r"(r) : "f"(a1), "f"(a0)); return r;
}
static __device__ __forceinline__ float bfres(float a) {
    return a - __bfloat162float(__float2bfloat16(a));
}
static __device__ __forceinline__ void mma16816(float c[4], const uint32_t a[4], const uint32_t b[2]) {
    asm("mma.sync.aligned.m16n8k16.row.col.f32.bf16.bf16.f32 "
        "{%0,%1,%2,%3}, {%4,%5,%6,%7}, {%8,%9}, {%0,%1,%2,%3};"
        : "+f"(c[0]), "+f"(c[1]), "+f"(c[2]), "+f"(c[3])
        : "r"(a[0]), "r"(a[1]), "r"(a[2]), "r"(a[3]), "r"(b[0]), "r"(b[1]));
}
static __device__ __forceinline__ float fast_tanh(float x) {
    float e, r;
    asm("ex2.approx.f32 %0, %1;" : "=f"(e) : "f"(x * 2.8853900817779268f));
    asm("rcp.approx.f32 %0, %1;" : "=f"(r) : "f"(e + 1.0f));
    return fmaf(-2.0f, r, 1.0f);
}

// ===== Phase 1: xp = x @ Wih^T, smem-staged bf16 hi/lo MMA.
// Block tile: M=64 (one b, 64 t's) x N=64 (j half), K=64. 128 threads, 4 warps (2M x 2N).
__global__ __launch_bounds__(128)
void xp_gemm(const float* __restrict__ x,
             const float* __restrict__ Wih_fw, const float* __restrict__ Wih_bw)
{
    // padded rows: 72 halves = 36 words -> bank = (4g+t)%32, conflict-free
    __shared__ uint32_t xs_h[64*36], xs_l[64*36], ws_h[64*36], ws_l[64*36];

    const int tid  = threadIdx.x;
    const int lane = tid & 31;
    const int wid  = tid >> 5;
    const int wm = wid & 1, wn = wid >> 1;
    const int g = lane >> 2, t4 = lane & 3;

    const int T  = blockIdx.x;
    const int b  = T >> 4;
    const int t0 = (T & 15) * 64;
    const int nhalf = blockIdx.y;
    const int dir   = blockIdx.z;

    const float* W    = (dir ? Wih_bw : Wih_fw) + nhalf * 64 * DIN;
    const float* xsrc = x + ((size_t)b * SLEN + t0) * DIN;

    // stage x and W (coalesced float4), convert to bf16 hi/lo
    #pragma unroll
    for (int i = 0; i < 8; ++i) {
        const int idx = tid + i * 128;        // float4 index, 0..1023
        const int row = idx >> 4;
        const int c4  = (idx & 15) * 4;
        const int w   = row * 36 + (c4 >> 1);
        float4 v = ((const float4*)xsrc)[idx];
        xs_h[w]   = bfpack(v.x, v.y);
        xs_h[w+1] = bfpack(v.z, v.w);
        xs_l[w]   = bfpack(bfres(v.x), bfres(v.y));
        xs_l[w+1] = bfpack(bfres(v.z), bfres(v.w));
        float4 u = ((const float4*)W)[idx];
        ws_h[w]   = bfpack(u.x, u.y);
        ws_h[w+1] = bfpack(u.z, u.w);
        ws_l[w]   = bfpack(bfres(u.x), bfres(u.y));
        ws_l[w+1] = bfpack(bfres(u.z), bfres(u.w));
    }
    __syncthreads();

    float acc[2][4][4];
    #pragma unroll
    for (int mt = 0; mt < 2; ++mt)
        #pragma unroll
        for (int nt = 0; nt < 4; ++nt)
            #pragma unroll
            for (int c = 0; c < 4; ++c) acc[mt][nt][c] = 0.0f;

    #pragma unroll
    for (int kc = 0; kc < 4; ++kc) {
        const int base = 8 * kc + t4;
        uint32_t ah[2][4], al[2][4], bh[4][2], bl[4][2];
        #pragma unroll
        for (int mt = 0; mt < 2; ++mt) {
            const int r = wm * 32 + mt * 16 + g;
            ah[mt][0] = xs_h[r*36 + base];       ah[mt][1] = xs_h[(r+8)*36 + base];
            ah[mt][2] = xs_h[r*36 + base + 4];   ah[mt][3] = xs_h[(r+8)*36 + base + 4];
            al[mt][0] = xs_l[r*36 + base];       al[mt][1] = xs_l[(r+8)*36 + base];
            al[mt][2] = xs_l[r*36 + base + 4];   al[mt][3] = xs_l[(r+8)*36 + base + 4];
        }
        #pragma unroll
        for (int nt = 0; nt < 4; ++nt) {
            const int n = wn * 32 + nt * 8 + g;
            bh[nt][0] = ws_h[n*36 + base];  bh[nt][1] = ws_h[n*36 + base + 4];
            bl[nt][0] = ws_l[n*36 + base];  bl[nt][1] = ws_l[n*36 + base + 4];
        }
        #pragma unroll
        for (int mt = 0; mt < 2; ++mt)
            #pragma unroll
            for (int nt = 0; nt < 4; ++nt) {
                mma16816(acc[mt][nt], ah[mt], bh[nt]);
                mma16816(acc[mt][nt], ah[mt], bl[nt]);
                mma16816(acc[mt][nt], al[mt], bh[nt]);
            }
    }

    // epilogue -> g_buf[dir][b>>3][t][b&7][j]
    const int bg = b >> 3, bi = b & 7;
    #pragma unroll
    for (int mt = 0; mt < 2; ++mt) {
        const int tr = t0 + wm * 32 + mt * 16 + g;
        float* base0 = g_buf + ((((size_t)dir * 32 + bg) * SLEN + tr) * 8 + bi) * HID;
        float* base1 = base0 + 8 * 8 * HID;     // tr + 8
        #pragma unroll
        for (int nt = 0; nt < 4; ++nt) {
            const int j = nhalf * 64 + wn * 32 + nt * 8 + 2 * t4;
            *(float2*)(base0 + j) = make_float2(acc[mt][nt][0], acc[mt][nt][1]);
            *(float2*)(base1 + j) = make_float2(acc[mt][nt][2], acc[mt][nt][3]);
        }
    }
}

// ===== Phase 2: tensor-core recurrence.
// 64 blocks (2 dirs x 32 batch groups of 8), 128 threads (4 warps).
// GEMM per step: D[j,b] = Whh[j,:] . h[b,:],  M=128(j) split 32/warp, N=8(batch), K=128.
// A (Whh, bf16 hi/lo) register-resident all steps. h passes between warps via smem bf16 hi/lo.
__global__ __launch_bounds__(128, 1)
void birnn_recur(const float* __restrict__ Whh_fw, const float* __restrict__ Whh_bw,
                 const float* __restrict__ bih_fw, const float* __restrict__ bhh_fw,
                 const float* __restrict__ bih_bw, const float* __restrict__ bhh_bw)
{
    // h tile: [batch 8][j 128] bf16, row stride 136 halves (68 words) -> conflict-free
    __shared__ unsigned short hb_h[8 * 136];
    __shared__ unsigned short hb_l[8 * 136];

    const int tid  = threadIdx.x;
    const int lane = tid & 31;
    const int w    = tid >> 5;
    const int g = lane >> 2, t4 = lane & 3;
    const int dir = blockIdx.x >> 5;
    const int bg  = blockIdx.x & 31;

    const float* Whh = dir ? Whh_bw : Whh_fw;
    const float* bih = dir ? bih_bw : bih_fw;
    const float* bhh = dir ? bhh_bw : bhh_fw;

    // static A fragments: Whh rows [32w, 32w+32), hi + lo
    uint32_t aWh[2][8][4], aWl[2][8][4];
    #pragma unroll
    for (int mt = 0; mt < 2; ++mt) {
        const int j0 = 32 * w + 16 * mt + g;
        #pragma unroll
        for (int kc = 0; kc < 8; ++kc) {
            const float* r0 = Whh + j0 * HID + 16 * kc + 2 * t4;
            const float* r1 = r0 + 8 * HID;
            float2 v0 = *(const float2*)r0;
            float2 v1 = *(const float2*)r1;
            float2 v2 = *(const float2*)(r0 + 8);
            float2 v3 = *(const float2*)(r1 + 8);
            aWh[mt][kc][0] = bfpack(v0.x, v0.y);  aWl[mt][kc][0] = bfpack(bfres(v0.x), bfres(v0.y));
            aWh[mt][kc][1] = bfpack(v1.x, v1.y);  aWl[mt][kc][1] = bfpack(bfres(v1.x), bfres(v1.y));
            aWh[mt][kc][2] = bfpack(v2.x, v2.y);  aWl[mt][kc][2] = bfpack(bfres(v2.x), bfres(v2.y));
            aWh[mt][kc][3] = bfpack(v3.x, v3.y);  aWl[mt][kc][3] = bfpack(bfres(v3.x), bfres(v3.y));
        }
    }

    float bias[2][2];
    #pragma unroll
    for (int mt = 0; mt < 2; ++mt)
        #pragma unroll
        for (int hh = 0; hh < 2; ++hh) {
            const int j = 32 * w + 16 * mt + g + 8 * hh;
            bias[mt][hh] = bih[j] + bhh[j];
        }

    // 8 owned (b,j) gmem offsets within the per-step 4KB blob
    int off[2][4];
    #pragma unroll
    for (int mt = 0; mt < 2; ++mt)
        #pragma unroll
        for (int e = 0; e < 4; ++e)
            off[mt][e] = (2 * t4 + (e & 1)) * HID + 32 * w + 16 * mt + g + 8 * (e >> 1);

    // zero h smem (h_0 = 0)
    for (int i = tid; i < 8 * 136; i += 128) { hb_h[i] = 0; hb_l[i] = 0; }

    const int t0 = dir ? (SLEN - 1) : 0;
    const int dt = dir ? -1 : 1;
    float* blob = g_buf + (((size_t)dir * 32 + bg) * SLEN + t0) * (8 * HID);
    const long bstride = (long)dt * 8 * HID;

    float xpv[2][4];
    #pragma unroll
    for (int mt = 0; mt < 2; ++mt)
        #pragma unroll
        for (int e = 0; e < 4; ++e) xpv[mt][e] = __ldg(blob + off[mt][e]);
    __syncthreads();

    const uint32_t* hbw_h = (const uint32_t*)hb_h;
    const uint32_t* hbw_l = (const uint32_t*)hb_l;

    for (int s = 0; s < SLEN; ++s) {
        // prefetch xp(t+1) — hidden under the MMA block
        float xpn[2][4];
        if (s + 1 < SLEN) {
            const float* nb = blob + bstride;
            #pragma unroll
            for (int mt = 0; mt < 2; ++mt)
                #pragma unroll
                for (int e = 0; e < 4; ++e) xpn[mt][e] = __ldg(nb + off[mt][e]);
        }

        // MMA: 3 hi/lo product sets, B fragments streamed from smem
        float acc0[2][4], acc1[2][4], acc2[2][4];
        #pragma unroll
        for (int mt = 0; mt < 2; ++mt)
            #pragma unroll
            for (int c = 0; c < 4; ++c) { acc0[mt][c] = 0.f; acc1[mt][c] = 0.f; acc2[mt][c] = 0.f; }

        #pragma unroll
        for (int kc = 0; kc < 8; ++kc) {
            const int w0 = g * 68 + 8 * kc + t4;
            uint32_t bfh[2], bfl[2];
            bfh[0] = hbw_h[w0];  bfh[1] = hbw_h[w0 + 4];
            bfl[0] = hbw_l[w0];  bfl[1] = hbw_l[w0 + 4];
            #pragma unroll
            for (int mt = 0; mt < 2; ++mt) {
                mma16816(acc0[mt], aWh[mt][kc], bfh);
                mma16816(acc1[mt], aWh[mt][kc], bfl);
                mma16816(acc2[mt], aWl[mt][kc], bfh);
            }
        }

        // combine + xp + bias + tanh
        float v[2][4];
        #pragma unroll
        for (int mt = 0; mt < 2; ++mt)
            #pragma unroll
            for (int e = 0; e < 4; ++e) {
                float sum = acc0[mt][e] + acc1[mt][e] + acc2[mt][e]
                          + xpv[mt][e] + bias[mt][e >> 1];
                v[mt][e] = fast_tanh(sum);
            }

        __syncthreads();   // all warps done reading smem h_t (MMA above)

        // write h: smem bf16 hi/lo for next step's B, gmem fp32 for fc pass
        #pragma unroll
        for (int mt = 0; mt < 2; ++mt)
            #pragma unroll
            for (int e = 0; e < 4; ++e) {
                const float val = v[mt][e];
                blob[off[mt][e]] = val;    // overwrite consumed xp[t] with h[t]
                const unsigned short hi = __bfloat16_as_ushort(__float2bfloat16(val));
                const float hif = __bfloat162float(__ushort_as_bfloat16(hi));
                const unsigned short lo = __bfloat16_as_ushort(__float2bfloat16(val - hif));
                const int b_in = 2 * t4 + (e & 1);
                const int j    = 32 * w + 16 * mt + g + 8 * (e >> 1);
                hb_h[b_in * 136 + j] = hi;
                hb_l[b_in * 136 + j] = lo;
            }

        blob += bstride;
        #pragma unroll
        for (int mt = 0; mt < 2; ++mt)
            #pragma unroll
            for (int e = 0; e < 4; ++e) xpv[mt][e] = xpn[mt][e];

        __syncthreads();   // h_{t+1} visible before next MMA reads it
    }
}

// ===== Phase 3: fc head. One warp per (b,t).
__global__ __launch_bounds__(256)
void birnn_fc(const float* __restrict__ fcW, const float* __restrict__ fcb,
              float* __restrict__ out)
{
    const int gw   = (blockIdx.x * blockDim.x + threadIdx.x) >> 5;
    const int lane = threadIdx.x & 31;
    const int b = gw >> 10;
    const int t = gw & 1023;
    const int bg = b >> 3, bi = b & 7;

    const float4* hf = (const float4*)(g_buf + ((((size_t)0 * 32 + bg) * SLEN + t) * 8 + bi) * HID);
    const float4* hb = (const float4*)(g_buf + ((((size_t)1 * 32 + bg) * SLEN + t) * 8 + bi) * HID);
    float4 a  = hf[lane];
    float4 c  = hb[lane];
    float4 wa = ((const float4*)fcW)[lane];
    float4 wb = ((const float4*)fcW)[32 + lane];

    float s = a.x*wa.x + a.y*wa.y + a.z*wa.z + a.w*wa.w
            + c.x*wb.x + c.y*wb.y + c.z*wb.z + c.w*wb.w;
    #pragma unroll
    for (int m = 16; m > 0; m >>= 1)
        s += __shfl_xor_sync(0xffffffffu, s, m);
    if (lane == 0) out[gw] = s + fcb[0];
}

extern "C" void kernel_launch(void* const* d_in, const int* in_sizes, int n_in,
                              void* d_out, int out_size)
{
    (void)in_sizes; (void)n_in; (void)out_size;
    const float* inputs = (const float*)d_in[0];
    const float* Wih_fw = (const float*)d_in[1];
    const float* Whh_fw = (const float*)d_in[2];
    const float* bih_fw = (const float*)d_in[3];
    const float* bhh_fw = (const float*)d_in[4];
    const float* Wih_bw = (const float*)d_in[5];
    const float* Whh_bw = (const float*)d_in[6];
    const float* bih_bw = (const float*)d_in[7];
    const float* bhh_bw = (const float*)d_in[8];
    const float* fcW    = (const float*)d_in[9];
    const float* fcb    = (const float*)d_in[10];
    float* out = (float*)d_out;

    xp_gemm<<<dim3(BATCH * (SLEN / 64), 2, 2), 128>>>(inputs, Wih_fw, Wih_bw);
    birnn_recur<<<64, 128>>>(Whh_fw, Whh_bw, bih_fw, bhh_fw, bih_bw, bhh_bw);
    birnn_fc<<<(BATCH * SLEN) / 8, 256>>>(fcW, fcb, out);
}

// round 6
// speedup vs baseline: 1.4628x; 1.2678x over previous
#include <cuda_runtime.h>
#include <cuda_bf16.h>
#include <cstdint>

#define SLEN 1024
#define BATCH 256
#define DIN 64
#define HID 128
#define KTOT 192          // [h | x]
#define KROW 200          // padded halves per B row (100 words)

// h outputs for fc pass: [dir][b][t][j]
__device__ float g_h[2u * BATCH * SLEN * HID];

typedef unsigned int u32;

static __device__ __forceinline__ u32 bfpack(float a0, float a1) {
    u32 r; asm("cvt.rn.bf16x2.f32 %0, %1, %2;" : "=r"(r) : "f"(a1), "f"(a0)); return r;
}
static __device__ __forceinline__ float bfres(float a) {
    return a - __bfloat162float(__float2bfloat16(a));
}
static __device__ __forceinline__ void mma16816(float c[4], const u32 a[4], const u32 b[2]) {
    asm("mma.sync.aligned.m16n8k16.row.col.f32.bf16.bf16.f32 "
        "{%0,%1,%2,%3}, {%4,%5,%6,%7}, {%8,%9}, {%0,%1,%2,%3};"
        : "+f"(c[0]), "+f"(c[1]), "+f"(c[2]), "+f"(c[3])
        : "r"(a[0]), "r"(a[1]), "r"(a[2]), "r"(a[3]), "r"(b[0]), "r"(b[1]));
}
static __device__ __forceinline__ float fast_tanh(float x) {
    float e, r;
    asm("ex2.approx.f32 %0, %1;" : "=f"(e) : "f"(x * 2.8853900817779268f));
    asm("rcp.approx.f32 %0, %1;" : "=f"(r) : "f"(e + 1.0f));
    return fmaf(-2.0f, r, 1.0f);
}

// ===== Recurrence: 64 blocks (2 dir x 32 batch-groups of 8), 256 threads (8 warps).
// Per step: D[j(128), b(8)] = [Whh|Wih] . [h|x], K=192, bf16 hi/lo 3-product fp32-emu.
// Warp w owns m16 tile j in [16w, 16w+16). A fragments register-resident all steps.
__global__ __launch_bounds__(256, 1)
void birnn_recur(const float* __restrict__ inputs,
                 const float* __restrict__ Whh_fw, const float* __restrict__ Whh_bw,
                 const float* __restrict__ Wih_fw, const float* __restrict__ Wih_bw,
                 const float* __restrict__ bih_fw, const float* __restrict__ bhh_fw,
                 const float* __restrict__ bih_bw, const float* __restrict__ bhh_bw)
{
    __shared__ unsigned short hb_h[8 * KROW];   // B hi: [batch 8][k 192 pad 200]
    __shared__ unsigned short hb_l[8 * KROW];   // B lo

    const int tid  = threadIdx.x;
    const int lane = tid & 31;
    const int w    = tid >> 5;
    const int g  = lane >> 2;      // 0..7
    const int t4 = lane & 3;       // 0..3
    const int j0 = 16 * w;
    const int dir = blockIdx.x >> 5;
    const int bb  = (blockIdx.x & 31) * 8;

    const float* Whh = dir ? Whh_bw : Whh_fw;
    const float* Wih = dir ? Wih_bw : Wih_fw;

    // ---- static A fragments: rows j0+g, j0+g+8 over K=192, hi+lo ----
    u32 ah[12][4], al[12][4];
    #pragma unroll
    for (int kc = 0; kc < 12; ++kc) {
        const int kb = 16 * kc + 2 * t4;
        const float* r0 = (kc < 8) ? (Whh + (j0 + g) * HID + kb)
                                   : (Wih + (j0 + g) * DIN + (kb - HID));
        const float* r1 = (kc < 8) ? (Whh + (j0 + g + 8) * HID + kb)
                                   : (Wih + (j0 + g + 8) * DIN + (kb - HID));
        float2 v0 = *(const float2*)r0;
        float2 v1 = *(const float2*)r1;
        float2 v2 = *(const float2*)(r0 + 8);
        float2 v3 = *(const float2*)(r1 + 8);
        ah[kc][0] = bfpack(v0.x, v0.y);  al[kc][0] = bfpack(bfres(v0.x), bfres(v0.y));
        ah[kc][1] = bfpack(v1.x, v1.y);  al[kc][1] = bfpack(bfres(v1.x), bfres(v1.y));
        ah[kc][2] = bfpack(v2.x, v2.y);  al[kc][2] = bfpack(bfres(v2.x), bfres(v2.y));
        ah[kc][3] = bfpack(v3.x, v3.y);  al[kc][3] = bfpack(bfres(v3.x), bfres(v3.y));
    }

    float bias2[2];
    #pragma unroll
    for (int hh = 0; hh < 2; ++hh) {
        const int j = j0 + g + 8 * hh;
        bias2[hh] = dir ? (bih_bw[j] + bhh_bw[j]) : (bih_fw[j] + bhh_fw[j]);
    }

    // ---- zero B tiles (h0 = 0) ----
    for (int i = tid; i < (8 * KROW * 2 * 2) / 4; i += 256)
        ((u32*)hb_h)[i] = 0;   // hb_h and hb_l are adjacent; zero both

    // ---- x loader assignment: thread -> (batch xb, dims 2*lane..) ----
    const int t0 = dir ? (SLEN - 1) : 0;
    const int dt = dir ? -1 : 1;
    const int xb = tid >> 5;                 // warp w loads batch row w
    const float* xptr = inputs + ((size_t)(bb + xb) * SLEN + t0) * DIN + lane * 2;
    const int xw = xb * 100 + 64 + lane;     // word index in B tile

    __syncthreads();
    {
        float2 v = *(const float2*)xptr;
        ((u32*)hb_h)[xw] = bfpack(v.x, v.y);
        ((u32*)hb_l)[xw] = bfpack(bfres(v.x), bfres(v.y));
    }
    __syncthreads();

    // ---- gmem h stream pointers ----
    float* gbase = g_h + ((size_t)(dir * BATCH + bb) * SLEN + t0) * HID;
    const long gstep = (long)dt * HID;
    int goff[4];
    #pragma unroll
    for (int e = 0; e < 4; ++e)
        goff[e] = (2 * t4 + (e & 1)) * (SLEN * HID) + j0 + g + 8 * (e >> 1);

    const u32* Hh = (const u32*)hb_h;
    const u32* Hl = (const u32*)hb_l;

    for (int s = 0; s < SLEN; ++s) {
        // ---- 36 HMMA over K=192, 3 independent accumulator chains ----
        float a0[4] = {0.f, 0.f, 0.f, 0.f};
        float a1[4] = {0.f, 0.f, 0.f, 0.f};
        float a2[4] = {0.f, 0.f, 0.f, 0.f};
        #pragma unroll
        for (int kc = 0; kc < 12; ++kc) {
            const int w0 = g * 100 + kc * 8 + t4;
            u32 bh[2], bl[2];
            bh[0] = Hh[w0];  bh[1] = Hh[w0 + 4];
            bl[0] = Hl[w0];  bl[1] = Hl[w0 + 4];
            mma16816(a0, ah[kc], bh);
            mma16816(a1, ah[kc], bl);
            mma16816(a2, al[kc], bh);
        }

        // ---- prefetch next x (hidden under MMA) ----
        float2 xn = make_float2(0.f, 0.f);
        if (s + 1 < SLEN) {
            xptr += dt * DIN;
            xn = *(const float2*)xptr;
        }

        // ---- activate ----
        float v[4];
        #pragma unroll
        for (int e = 0; e < 4; ++e)
            v[e] = fast_tanh(a0[e] + a1[e] + a2[e] + bias2[e >> 1]);

        __syncthreads();   // all B reads (LDS above) complete

        // ---- write B <- [h_{s+1} | x_{s+1}] hi/lo, stream h to gmem ----
        #pragma unroll
        for (int e = 0; e < 4; ++e) {
            const int b_ = 2 * t4 + (e & 1);
            const int j_ = j0 + g + 8 * (e >> 1);
            const __nv_bfloat16 hi = __float2bfloat16(v[e]);
            const float hif = __bfloat162float(hi);
            const __nv_bfloat16 lo = __float2bfloat16(v[e] - hif);
            hb_h[b_ * KROW + j_] = __bfloat16_as_ushort(hi);
            hb_l[b_ * KROW + j_] = __bfloat16_as_ushort(lo);
            gbase[goff[e]] = v[e];
        }
        ((u32*)hb_h)[xw] = bfpack(xn.x, xn.y);
        ((u32*)hb_l)[xw] = bfpack(bfres(xn.x), bfres(xn.y));
        gbase += gstep;

        __syncthreads();   // B ready for next step
    }
}

// ===== fc head: out[b][t] = fcb + <h_fw,fcW[0:128]> + <h_bw,fcW[128:256]>
__global__ __launch_bounds__(256)
void birnn_fc(const float* __restrict__ fcW, const float* __restrict__ fcb,
              float* __restrict__ out)
{
    const int gw   = (blockIdx.x * blockDim.x + threadIdx.x) >> 5;
    const int lane = threadIdx.x & 31;
    const int b = gw >> 10;
    const int t = gw & 1023;

    const float4* hf = (const float4*)(g_h + ((size_t)b * SLEN + t) * HID);
    const float4* hb = (const float4*)(g_h + ((size_t)(BATCH + b) * SLEN + t) * HID);
    float4 a  = hf[lane];
    float4 c  = hb[lane];
    float4 wa = ((const float4*)fcW)[lane];
    float4 wb = ((const float4*)fcW)[32 + lane];

    float s = a.x*wa.x + a.y*wa.y + a.z*wa.z + a.w*wa.w
            + c.x*wb.x + c.y*wb.y + c.z*wb.z + c.w*wb.w;
    #pragma unroll
    for (int m = 16; m > 0; m >>= 1)
        s += __shfl_xor_sync(0xffffffffu, s, m);
    if (lane == 0) out[gw] = s + fcb[0];
}

extern "C" void kernel_launch(void* const* d_in, const int* in_sizes, int n_in,
                              void* d_out, int out_size)
{
    (void)in_sizes; (void)n_in; (void)out_size;
    const float* inputs = (const float*)d_in[0];
    const float* Wih_fw = (const float*)d_in[1];
    const float* Whh_fw = (const float*)d_in[2];
    const float* bih_fw = (const float*)d_in[3];
    const float* bhh_fw = (const float*)d_in[4];
    const float* Wih_bw = (const float*)d_in[5];
    const float* Whh_bw = (const float*)d_in[6];
    const float* bih_bw = (const float*)d_in[7];
    const float* bhh_bw = (const float*)d_in[8];
    const float* fcW    = (const float*)d_in[9];
    const float* fcb    = (const float*)d_in[10];
    float* out = (float*)d_out;

    birnn_recur<<<64, 256>>>(inputs, Whh_fw, Whh_bw, Wih_fw, Wih_bw,
                             bih_fw, bhh_fw, bih_bw, bhh_bw);
    birnn_fc<<<(BATCH * SLEN) / 8, 256>>>(fcW, fcb, out);
}